// round 7
// baseline (speedup 1.0000x reference)
#include <cuda_runtime.h>

#define GW    40
#define LL    1600          // GW*GW
#define VV    64
#define PITCH 41            // padded row pitch -> conflict-free column access
#define NPAD  (GW * PITCH)  // 1640
#define NT    512
#define INFV  1000000000.0f
#define BIGL  (1 << 20)

__device__ double2 g_part[1024];

// Schraudolph fast exp (~3% max rel err, FFMA+F2I, no MUFU).
// Only feeds the cost field consumed by the discrete path mask.
__device__ __forceinline__ float fexp(float x) {
    int i = __float2int_rn(12102203.0f * x + 1064866805.0f);
    return __int_as_float(i);
}

__global__ void __launch_bounds__(NT) loss_batch_kernel(
    const float* __restrict__ logits, const int* __restrict__ labels)
{
    const int b   = blockIdx.x;
    const int tid = threadIdx.x;

    __shared__ float         s_cost[NPAD];   // aliased as int labels in phase 5
    __shared__ float         s_dist[NPAD];
    __shared__ unsigned char s_road[NPAD];
    __shared__ unsigned char s_pred[NPAD];
    __shared__ unsigned char s_mask[NPAD];
    __shared__ unsigned char s_true[NPAD];
    __shared__ int s_start, s_end, s_flag;
    __shared__ int s_tc, s_pc, s_fp, s_n1, s_comp;

    if (tid == 0) {
        s_start = 1 << 29; s_end = 1 << 29; s_flag = 0;
        s_tc = 0; s_pc = 0; s_fp = 0; s_n1 = 0; s_comp = 0;
    }
    if (tid < GW) {  // pad column
        int ip = tid * PITCH + GW;
        s_road[ip] = 0; s_pred[ip] = 0; s_mask[ip] = 0; s_true[ip] = 0;
    }
    __syncthreads();

    // ---- Phase 1: labels -> road/true, start/end (first occurrence), tc ----
    int tc_loc = 0;
    for (int cell = tid; cell < LL; cell += NT) {
        int i41 = cell + cell / GW;
        int lb  = labels[(long)b * LL + cell];
        s_road[i41] = (lb != 1);
        bool tr = (lb == 9);
        s_true[i41] = tr;
        s_mask[i41] = 0;
        tc_loc += tr ? 1 : 0;
        if (lb == 7) atomicMin(&s_start, i41);
        if (lb == 8) atomicMin(&s_end, i41);
    }
    tc_loc = (int)__reduce_add_sync(0xffffffffu, (unsigned)tc_loc);
    if ((tid & 31) == 0) atomicAdd(&s_tc, tc_loc);
    __syncthreads();

    // ---- Phase 2: softmax cost (approx) + exact argmax pred + counts ----
    int pc_loc = 0, fp_loc = 0;
    for (int cell = tid; cell < LL; cell += NT) {
        const float4* p4 = (const float4*)(logits + ((long)b * LL + cell) * VV);
        float s0 = 0.f, s1 = 0.f, s2 = 0.f, s3 = 0.f;
        float mlo = -INFV, mhi = -INFV, v9 = 0.f;
        #pragma unroll
        for (int g = 0; g < 16; ++g) {
            float4 v = p4[g];
            s0 += fexp(v.x); s1 += fexp(v.y); s2 += fexp(v.z); s3 += fexp(v.w);
            if (g < 2) {                       // idx 0..7
                mlo = fmaxf(mlo, fmaxf(fmaxf(v.x, v.y), fmaxf(v.z, v.w)));
            } else if (g == 2) {               // idx 8..11
                mlo = fmaxf(mlo, v.x);
                v9  = v.y;
                mhi = fmaxf(v.z, v.w);
            } else {                           // idx 12..63
                mhi = fmaxf(mhi, fmaxf(fmaxf(v.x, v.y), fmaxf(v.z, v.w)));
            }
        }
        float sum  = (s0 + s1) + (s2 + s3);
        float p    = __fdividef(fexp(v9), sum);
        float cost = -__logf(fmaxf(p, 1e-6f));
        bool pr = (v9 > mlo) && (v9 >= mhi);   // argmax==9, first-max tie rule
        int i41 = cell + cell / GW;
        s_cost[i41] = cost;
        s_pred[i41] = pr;
        pc_loc += pr ? 1 : 0;
        fp_loc += (pr && !s_true[i41]) ? 1 : 0;
    }
    pc_loc = (int)__reduce_add_sync(0xffffffffu, (unsigned)pc_loc);
    fp_loc = (int)__reduce_add_sync(0xffffffffu, (unsigned)fp_loc);
    if ((tid & 31) == 0) { atomicAdd(&s_pc, pc_loc); atomicAdd(&s_fp, fp_loc); }

    // ---- Phase 3: SSSP via Gauss-Seidel directional sweeps ----
    for (int i = tid; i < NPAD; i += NT) s_dist[i] = INFV;
    __syncthreads();
    const int sIdx = (s_start < (1 << 29)) ? s_start : 0;
    const int eIdx = (s_end   < (1 << 29)) ? s_end   : 0;
    if (tid == 0) s_dist[sIdx] = 0.0f;
    __syncthreads();

    for (int round = 1; round <= LL; ++round) {
        bool chg = false;
        if (tid < GW) {               // DOWN
            const int c = tid;
            float carry = s_dist[c];
            for (int r = 1; r < GW; ++r) {
                int i = r * PITCH + c;
                float d = s_dist[i];
                if (s_road[i]) {
                    float cand = (carry + s_cost[i]) + 1.0f;
                    if (cand < d) { d = cand; s_dist[i] = d; chg = true; }
                }
                carry = d;
            }
        }
        __syncthreads();
        if (tid < GW) {               // UP
            const int c = tid;
            float carry = s_dist[(GW - 1) * PITCH + c];
            for (int r = GW - 2; r >= 0; --r) {
                int i = r * PITCH + c;
                float d = s_dist[i];
                if (s_road[i]) {
                    float cand = (carry + s_cost[i]) + 1.0f;
                    if (cand < d) { d = cand; s_dist[i] = d; chg = true; }
                }
                carry = d;
            }
        }
        __syncthreads();
        if (tid < GW) {               // RIGHT
            const int base = tid * PITCH;
            float carry = s_dist[base];
            for (int c = 1; c < GW; ++c) {
                int i = base + c;
                float d = s_dist[i];
                if (s_road[i]) {
                    float cand = (carry + s_cost[i]) + 1.0f;
                    if (cand < d) { d = cand; s_dist[i] = d; chg = true; }
                }
                carry = d;
            }
        }
        __syncthreads();
        if (tid < GW) {               // LEFT
            const int base = tid * PITCH;
            float carry = s_dist[base + GW - 1];
            for (int c = GW - 2; c >= 0; --c) {
                int i = base + c;
                float d = s_dist[i];
                if (s_road[i]) {
                    float cand = (carry + s_cost[i]) + 1.0f;
                    if (cand < d) { d = cand; s_dist[i] = d; chg = true; }
                }
                carry = d;
            }
        }
        if (chg) s_flag = round;
        __syncthreads();
        if (s_flag != round) break;   // uniform decision
        __syncthreads();
    }

    // ---- Phase 4: greedy backtrace (thread 0), reference tie-break order ----
    if (tid == 0) {
        bool done = !(s_dist[eIdx] < 5.0e8f);
        int pos = eIdx;
        for (int step = 0; step < LL && !done; ++step) {
            s_mask[pos] = 1;
            if (pos == sIdx) break;
            int r = pos / PITCH, c = pos - r * PITCH;
            float best; int bi;
            {   // j=0: (r, c+1)
                bool val = (c + 1 < GW);
                int ci = r * PITCH + (val ? c + 1 : GW - 1);
                best = val ? s_dist[ci] : INFV; bi = ci;
            }
            {   // j=1: (r, c-1)
                bool val = (c - 1 >= 0);
                int ci = r * PITCH + (val ? c - 1 : 0);
                float nd = val ? s_dist[ci] : INFV;
                if (nd < best) { best = nd; bi = ci; }
            }
            {   // j=2: (r+1, c)
                bool val = (r + 1 < GW);
                int ci = (val ? r + 1 : GW - 1) * PITCH + c;
                float nd = val ? s_dist[ci] : INFV;
                if (nd < best) { best = nd; bi = ci; }
            }
            {   // j=3: (r-1, c)
                bool val = (r - 1 >= 0);
                int ci = (val ? r - 1 : 0) * PITCH + c;
                float nd = val ? s_dist[ci] : INFV;
                if (nd < best) { best = nd; bi = ci; }
            }
            pos = bi;
        }
    }
    __syncthreads();

    int n1_loc = 0;
    for (int i = tid; i < NPAD; i += NT) n1_loc += s_mask[i];
    n1_loc = (int)__reduce_add_sync(0xffffffffu, (unsigned)n1_loc);
    if ((tid & 31) == 0) atomicAdd(&s_n1, n1_loc);

    // ---- Phase 5: connected components (min-label GS sweeps) ----
    int* s_lab = (int*)s_cost;  // cost no longer needed
    for (int i = tid; i < NPAD; i += NT) s_lab[i] = s_pred[i] ? i : BIGL;
    if (tid == 0) s_flag = 0;
    __syncthreads();

    for (int round = 1; round <= LL; ++round) {
        bool chg = false;
        if (tid < GW) {               // DOWN
            const int c = tid;
            int carry = s_pred[c] ? s_lab[c] : BIGL;
            for (int r = 1; r < GW; ++r) {
                int i = r * PITCH + c;
                if (s_pred[i]) {
                    int l = s_lab[i];
                    if (carry < l) { l = carry; s_lab[i] = l; chg = true; }
                    carry = l;
                } else carry = BIGL;
            }
        }
        __syncthreads();
        if (tid < GW) {               // UP
            const int c = tid;
            int i0 = (GW - 1) * PITCH + c;
            int carry = s_pred[i0] ? s_lab[i0] : BIGL;
            for (int r = GW - 2; r >= 0; --r) {
                int i = r * PITCH + c;
                if (s_pred[i]) {
                    int l = s_lab[i];
                    if (carry < l) { l = carry; s_lab[i] = l; chg = true; }
                    carry = l;
                } else carry = BIGL;
            }
        }
        __syncthreads();
        if (tid < GW) {               // RIGHT
            const int base = tid * PITCH;
            int carry = s_pred[base] ? s_lab[base] : BIGL;
            for (int c = 1; c < GW; ++c) {
                int i = base + c;
                if (s_pred[i]) {
                    int l = s_lab[i];
                    if (carry < l) { l = carry; s_lab[i] = l; chg = true; }
                    carry = l;
                } else carry = BIGL;
            }
        }
        __syncthreads();
        if (tid < GW) {               // LEFT
            const int base = tid * PITCH;
            int i0 = base + GW - 1;
            int carry = s_pred[i0] ? s_lab[i0] : BIGL;
            for (int c = GW - 2; c >= 0; --c) {
                int i = base + c;
                if (s_pred[i]) {
                    int l = s_lab[i];
                    if (carry < l) { l = carry; s_lab[i] = l; chg = true; }
                    carry = l;
                } else carry = BIGL;
            }
        }
        if (chg) s_flag = round;
        __syncthreads();
        if (s_flag != round) break;
        __syncthreads();
    }

    int comp_loc = 0;
    for (int i = tid; i < NPAD; i += NT)
        comp_loc += (s_pred[i] && s_lab[i] == i) ? 1 : 0;
    comp_loc = (int)__reduce_add_sync(0xffffffffu, (unsigned)comp_loc);
    if ((tid & 31) == 0) atomicAdd(&s_comp, comp_loc);
    __syncthreads();

    // ---- Phase 6: per-batch contribution ----
    if (tid == 0) {
        double pc = (double)s_pc, fp = (double)s_fp, tc = (double)s_tc;
        double conn = (s_pc > 1) ? (double)((s_comp - 1 > 0) ? s_comp - 1 : 0) : 0.0;
        double cov  = fp / ((pc > 1.0) ? pc : 1.0);
        double bud  = fabs(pc - tc) * (1.0 / (double)LL);
        g_part[b] = make_double2(conn + cov + bud, (double)s_n1);
    }
}

__global__ void finalize_kernel(float* out, int B) {
    __shared__ double sh_a[8], sh_n[8];
    int t = threadIdx.x;
    double a = 0.0, n = 0.0;
    for (int i = t; i < B; i += 256) { double2 v = g_part[i]; a += v.x; n += v.y; }
    #pragma unroll
    for (int o = 16; o; o >>= 1) {
        a += __shfl_down_sync(0xffffffffu, a, o);
        n += __shfl_down_sync(0xffffffffu, n, o);
    }
    if ((t & 31) == 0) { sh_a[t >> 5] = a; sh_n[t >> 5] = n; }
    __syncthreads();
    if (t == 0) {
        a = 0.0; n = 0.0;
        #pragma unroll
        for (int w = 0; w < 8; ++w) { a += sh_a[w]; n += sh_n[w]; }
        // projection = ln2 + N1*(softplus(1)-1-ln2)/(B*L)
        double proj = 0.6931471805599453 + n * (-0.37988549304172247) / ((double)B * (double)LL);
        out[0] = (float)(proj + a / (double)B);
    }
}

extern "C" void kernel_launch(void* const* d_in, const int* in_sizes, int n_in,
                              void* d_out, int out_size) {
    const float* logits = (const float*)d_in[0];
    const int*   labels = (const int*)d_in[1];
    int B = in_sizes[1] / LL;
    loss_batch_kernel<<<B, NT>>>(logits, labels);
    finalize_kernel<<<1, 256>>>((float*)d_out, B);
}

// round 17
// speedup vs baseline: 2.3520x; 2.3520x over previous
#include <cuda_runtime.h>

#define GW    40
#define LL    1600
#define PITCH 41
#define NPAD  (GW * PITCH)   // 1640
#define INFV  1000000000.0f
#define BIGC  (1 << 29)
#define BIGL  (1 << 20)
#define MAXB  1024
#define SS    184.6650f      // 2^7 / ln2
#define CC    12599168.0f    // 16256 (bf16 bias<<7) + 12582912 (1.5*2^23 magic)

__device__ float         g_w[MAXB * LL];
__device__ unsigned char g_pr[MAXB * LL];
__device__ int4          g_cnt[MAXB * 2];  // tc, pc, fp per half-block
__device__ int2          g_se[MAXB * 2];   // start,end cell (raw index) per half
__device__ int           g_n1[MAXB];
__device__ int           g_comp[MAXB];

__device__ __forceinline__ unsigned bfadd2(unsigned a, unsigned b) {
    unsigned r; asm("add.rn.bf16x2 %0,%1,%2;" : "=r"(r) : "r"(a), "r"(b)); return r;
}
__device__ __forceinline__ unsigned bfmax2(unsigned a, unsigned b) {
    unsigned r; asm("max.bf16x2 %0,%1,%2;" : "=r"(r) : "r"(a), "r"(b)); return r;
}

// ---------------- K1: labels + softmax cost + exact pred + counts ----------
__global__ void __launch_bounds__(512) k1(const float* __restrict__ logits,
                                          const int* __restrict__ labels, int B) {
    const int b   = blockIdx.y;
    const int tid = threadIdx.x;
    const int c0  = blockIdx.x * (LL / 2);
    __shared__ int sh_tc, sh_pc, sh_fp, sh_s, sh_e;
    if (tid == 0) { sh_tc = 0; sh_pc = 0; sh_fp = 0; sh_s = BIGC; sh_e = BIGC; }
    __syncthreads();

    int tc = 0, pc = 0, fp = 0;
    for (int cell = c0 + tid; cell < c0 + LL / 2; cell += 512) {
        int  lb   = labels[b * LL + cell];
        bool road = (lb != 1), tr = (lb == 9);
        tc += tr;
        if (lb == 7) atomicMin(&sh_s, cell);
        if (lb == 8) atomicMin(&sh_e, cell);

        const float4* p4 = (const float4*)(logits + ((long)b * LL + cell) * 64);
        unsigned a0 = 0, a1 = 0, bm = 0;
        float v9 = 0.f;
        #pragma unroll
        for (int g = 0; g < 16; ++g) {
            float4 v = p4[g];
            if (g == 2) v9 = v.y;
            // bf16 Schraudolph exp via magic-add: lo16(bits) = bf16(e^x)
            unsigned y0 = __float_as_uint(fmaf(v.x, SS, CC));
            unsigned y1 = __float_as_uint(fmaf(v.y, SS, CC));
            unsigned y2 = __float_as_uint(fmaf(v.z, SS, CC));
            unsigned y3 = __float_as_uint(fmaf(v.w, SS, CC));
            unsigned p01 = __byte_perm(y0, y1, 0x5410);
            unsigned p23 = __byte_perm(y2, y3, 0x5410);
            a0 = bfadd2(a0, p01);
            a1 = bfadd2(a1, p23);
            bm = bfmax2(bm, p01);
            bm = bfmax2(bm, p23);
        }
        float sum = (__uint_as_float(a0 << 16) + __uint_as_float(a0 & 0xFFFF0000u))
                  + (__uint_as_float(a1 << 16) + __uint_as_float(a1 & 0xFFFF0000u));
        float cost = fminf(__logf(sum) - v9, 13.815511f);   // = -log(max(p,1e-6))

        // argmax screen (monotone map => no false negatives), exact recheck
        int vb = (int)(__float_as_uint(fmaf(v9, SS, CC)) & 0xFFFFu);
        int mm = max((int)(bm & 0xFFFFu), (int)(bm >> 16));
        bool pr = false;
        if (vb >= mm) {
            float mlo = -INFV, mhi = -INFV;
            #pragma unroll
            for (int g = 0; g < 16; ++g) {
                float4 v = p4[g];
                if (g < 2)       mlo = fmaxf(mlo, fmaxf(fmaxf(v.x, v.y), fmaxf(v.z, v.w)));
                else if (g == 2) { mlo = fmaxf(mlo, v.x); mhi = fmaxf(v.z, v.w); }
                else             mhi = fmaxf(mhi, fmaxf(fmaxf(v.x, v.y), fmaxf(v.z, v.w)));
            }
            pr = (v9 > mlo) && (v9 >= mhi);   // first-occurrence tie rule, exact
        }
        pc += pr; fp += (pr && !tr);
        g_pr[b * LL + cell] = pr;
        g_w[b * LL + cell]  = road ? (cost + 1.0f) : 1e18f;
    }
    tc = (int)__reduce_add_sync(~0u, (unsigned)tc);
    pc = (int)__reduce_add_sync(~0u, (unsigned)pc);
    fp = (int)__reduce_add_sync(~0u, (unsigned)fp);
    if ((tid & 31) == 0) { atomicAdd(&sh_tc, tc); atomicAdd(&sh_pc, pc); atomicAdd(&sh_fp, fp); }
    __syncthreads();
    if (tid == 0) {
        int h = b * 2 + blockIdx.x;
        g_cnt[h] = make_int4(sh_tc, sh_pc, sh_fp, 0);
        g_se[h]  = make_int2(sh_s, sh_e);
    }
}

// ---------------- K2: SSSP+backtrace (blocks 0..B-1) | components (B..2B-1) --
__global__ void __launch_bounds__(64) k2(int B) {
    const int tid = threadIdx.x;
    __shared__ float         sA[NPAD];   // w  (SSSP)  |  labels int alias (comp)
    __shared__ float         sD[NPAD];   // dist
    __shared__ unsigned char sM[NPAD];   // mask (SSSP) | pred (comp)
    __shared__ int s_flag, s_cnt;
    if (tid == 0) { s_flag = 0; s_cnt = 0; }

    if (blockIdx.x < B) {
        // ---------------- SSSP + greedy backtrace + n1 ----------------
        const int b = blockIdx.x;
        for (int i = tid; i < NPAD; i += 64) { sD[i] = INFV; sA[i] = 1e18f; sM[i] = 0; }
        __syncthreads();
        for (int i = tid; i < LL; i += 64) sA[i + i / GW] = g_w[b * LL + i];
        int2 h0 = g_se[2 * b], h1 = g_se[2 * b + 1];
        int  sc = min(h0.x, h1.x), ec = min(h0.y, h1.y);
        const int sIdx = (sc < BIGC) ? sc + sc / GW : 0;
        const int eIdx = (ec < BIGC) ? ec + ec / GW : 0;
        __syncthreads();
        if (tid == 0) sD[sIdx] = 0.f;
        __syncthreads();

        for (int round = 1; round <= LL; ++round) {
            float delta = 0.f;
            if (tid < GW) {                 // DOWN
                int c = tid; float carry = sD[c];
                for (int r = 1; r < GW; ++r) { int i = r * PITCH + c;
                    float o = sD[i]; float nd = fminf(o, carry + sA[i]);
                    sD[i] = nd; delta += o - nd; carry = nd; }
            }
            __syncthreads();
            if (tid < GW) {                 // UP
                int c = tid; float carry = sD[(GW - 1) * PITCH + c];
                for (int r = GW - 2; r >= 0; --r) { int i = r * PITCH + c;
                    float o = sD[i]; float nd = fminf(o, carry + sA[i]);
                    sD[i] = nd; delta += o - nd; carry = nd; }
            }
            __syncthreads();
            if (tid < GW) {                 // RIGHT
                int base = tid * PITCH; float carry = sD[base];
                for (int c = 1; c < GW; ++c) { int i = base + c;
                    float o = sD[i]; float nd = fminf(o, carry + sA[i]);
                    sD[i] = nd; delta += o - nd; carry = nd; }
            }
            __syncthreads();
            if (tid < GW) {                 // LEFT
                int base = tid * PITCH; float carry = sD[base + GW - 1];
                for (int c = GW - 2; c >= 0; --c) { int i = base + c;
                    float o = sD[i]; float nd = fminf(o, carry + sA[i]);
                    sD[i] = nd; delta += o - nd; carry = nd; }
            }
            if (delta != 0.f) s_flag = round;
            __syncthreads();
            if (s_flag != round) break;
        }

        if (tid == 0) {                     // backtrace, reference argmin order
            bool done = !(sD[eIdx] < 5.0e8f);
            int pos = eIdx;
            for (int step = 0; step < LL && !done; ++step) {
                sM[pos] = 1;
                if (pos == sIdx) break;
                int r = pos / PITCH, c = pos - r * PITCH;
                float best; int bi;
                { bool val = (c + 1 < GW); int ci = r * PITCH + (val ? c + 1 : GW - 1);
                  best = val ? sD[ci] : INFV; bi = ci; }
                { bool val = (c - 1 >= 0); int ci = r * PITCH + (val ? c - 1 : 0);
                  float nd = val ? sD[ci] : INFV; if (nd < best) { best = nd; bi = ci; } }
                { bool val = (r + 1 < GW); int ci = (val ? r + 1 : GW - 1) * PITCH + c;
                  float nd = val ? sD[ci] : INFV; if (nd < best) { best = nd; bi = ci; } }
                { bool val = (r - 1 >= 0); int ci = (val ? r - 1 : 0) * PITCH + c;
                  float nd = val ? sD[ci] : INFV; if (nd < best) { best = nd; bi = ci; } }
                pos = bi;
            }
        }
        __syncthreads();
        int n1 = 0;
        for (int i = tid; i < NPAD; i += 64) n1 += sM[i];
        n1 = (int)__reduce_add_sync(~0u, (unsigned)n1);
        if ((tid & 31) == 0) atomicAdd(&s_cnt, n1);
        __syncthreads();
        if (tid == 0) g_n1[b] = s_cnt;
    } else {
        // ---------------- connected components of pred ----------------
        const int b = blockIdx.x - B;
        int* sL = (int*)sA;
        for (int i = tid; i < NPAD; i += 64) { sL[i] = BIGL; sM[i] = 0; }
        __syncthreads();
        for (int i = tid; i < LL; i += 64) {
            unsigned char p = g_pr[b * LL + i];
            int i41 = i + i / GW;
            sM[i41] = p; sL[i41] = p ? i41 : BIGL;
        }
        __syncthreads();

        for (int round = 1; round <= LL; ++round) {
            int delta = 0;
            if (tid < GW) {                 // DOWN
                int c = tid; int carry = sL[c];
                for (int r = 1; r < GW; ++r) { int i = r * PITCH + c;
                    int o = sL[i]; int nd = sM[i] ? min(o, carry) : o;
                    sL[i] = nd; delta += o - nd; carry = nd; }
            }
            __syncthreads();
            if (tid < GW) {                 // UP
                int c = tid; int carry = sL[(GW - 1) * PITCH + c];
                for (int r = GW - 2; r >= 0; --r) { int i = r * PITCH + c;
                    int o = sL[i]; int nd = sM[i] ? min(o, carry) : o;
                    sL[i] = nd; delta += o - nd; carry = nd; }
            }
            __syncthreads();
            if (tid < GW) {                 // RIGHT
                int base = tid * PITCH; int carry = sL[base];
                for (int c = 1; c < GW; ++c) { int i = base + c;
                    int o = sL[i]; int nd = sM[i] ? min(o, carry) : o;
                    sL[i] = nd; delta += o - nd; carry = nd; }
            }
            __syncthreads();
            if (tid < GW) {                 // LEFT
                int base = tid * PITCH; int carry = sL[base + GW - 1];
                for (int c = GW - 2; c >= 0; --c) { int i = base + c;
                    int o = sL[i]; int nd = sM[i] ? min(o, carry) : o;
                    sL[i] = nd; delta += o - nd; carry = nd; }
            }
            if (delta != 0) s_flag = round;
            __syncthreads();
            if (s_flag != round) break;
        }
        int comp = 0;
        for (int i = tid; i < NPAD; i += 64) comp += (sM[i] && sL[i] == i);
        comp = (int)__reduce_add_sync(~0u, (unsigned)comp);
        if ((tid & 31) == 0) atomicAdd(&s_cnt, comp);
        __syncthreads();
        if (tid == 0) g_comp[b] = s_cnt;
    }
}

// ---------------- K3: finalize ----------------
__global__ void k3(float* out, int B) {
    __shared__ double sh_a[8], sh_n[8];
    int t = threadIdx.x;
    double a = 0.0, n = 0.0;
    for (int b = t; b < B; b += 256) {
        int4 c0 = g_cnt[2 * b], c1 = g_cnt[2 * b + 1];
        double tc = c0.x + c1.x, pc = c0.y + c1.y, fp = c0.z + c1.z;
        int comp = g_comp[b];
        double conn = (pc > 1.0) ? (double)((comp - 1 > 0) ? comp - 1 : 0) : 0.0;
        double cov  = fp / ((pc > 1.0) ? pc : 1.0);
        double bud  = fabs(pc - tc) * (1.0 / (double)LL);
        a += conn + cov + bud;
        n += (double)g_n1[b];
    }
    #pragma unroll
    for (int o = 16; o; o >>= 1) {
        a += __shfl_down_sync(0xffffffffu, a, o);
        n += __shfl_down_sync(0xffffffffu, n, o);
    }
    if ((t & 31) == 0) { sh_a[t >> 5] = a; sh_n[t >> 5] = n; }
    __syncthreads();
    if (t == 0) {
        a = 0.0; n = 0.0;
        #pragma unroll
        for (int w = 0; w < 8; ++w) { a += sh_a[w]; n += sh_n[w]; }
        double proj = 0.6931471805599453 + n * (-0.37988549304172247) / ((double)B * (double)LL);
        out[0] = (float)(proj + a / (double)B);
    }
}

extern "C" void kernel_launch(void* const* d_in, const int* in_sizes, int n_in,
                              void* d_out, int out_size) {
    const float* logits = (const float*)d_in[0];
    const int*   labels = (const int*)d_in[1];
    int B = in_sizes[1] / LL;
    k1<<<dim3(2, B), 512>>>(logits, labels, B);
    k2<<<2 * B, 64>>>(B);
    k3<<<1, 256>>>((float*)d_out, B);
}